// round 9
// baseline (speedup 1.0000x reference)
#include <cuda_runtime.h>
#include <cuda_bf16.h>
#include <cstdint>

// Problem constants (fixed by dataset):
//   walk:  int32 [B=1024, L=80]
//   neg:   int32 [B=1024, A=76, NEG=4]
//   embed: f32   [1000000, D=128]
//   out:   f32 scalar = (sum softplus(-pos) + sum softplus(neg)) / (B*A*8)
#define L_WALK   80
#define W_WIN    5
#define A_ANC    (L_WALK - W_WIN + 1)     // 76
#define NNEG     4
#define DIM      128
#define NVEC     (DIM / 4)                // 32 float4 per row
#define NTHREADS 256
#define NWARPS   (NTHREADS / 32)

#define SPLIT    2
#define ANC_PER  (A_ANC / SPLIT)          // 38 anchors per block
#define ROWS_PER (ANC_PER + W_WIN - 1)    // 42 walk rows staged per block
#define STAGE_V  (ROWS_PER * NVEC)        // 1344 float4 copies per block

static __global__ void zero_kernel(float* out) {
    if (threadIdx.x == 0) out[0] = 0.0f;
}

__device__ __forceinline__ float warp_reduce_sum(float v) {
    v += __shfl_xor_sync(0xffffffffu, v, 16);
    v += __shfl_xor_sync(0xffffffffu, v, 8);
    v += __shfl_xor_sync(0xffffffffu, v, 4);
    v += __shfl_xor_sync(0xffffffffu, v, 2);
    v += __shfl_xor_sync(0xffffffffu, v, 1);
    return v;
}

// Pairwise combining reduce: lanes with (lane & off)==0 end up holding the
// a-reduction, lanes with the bit set hold the b-reduction.
__device__ __forceinline__ float cmb(float a, float b, int off, int lane) {
    float send = (lane & off) ? a : b;
    float keep = (lane & off) ? b : a;
    return keep + __shfl_xor_sync(0xffffffffu, send, off);
}

// softplus(x) = max(x,0) + log(1 + exp(-|x|)); fast-math variants are
// accurate to ~1e-7 absolute here, far inside the 1e-3 rel-err budget.
__device__ __forceinline__ float softplus_f(float x) {
    return fmaxf(x, 0.0f) + __logf(1.0f + __expf(-fabsf(x)));
}

__device__ __forceinline__ float dot4(float4 a, float4 b) {
    return a.x * b.x + a.y * b.y + a.z * b.z + a.w * b.w;
}

// 16-byte global->shared async copy (LDGSTS, .cg = L1-bypass streaming).
__device__ __forceinline__ void cp_async16(void* smem_dst, const void* gmem_src) {
    uint32_t s = (uint32_t)__cvta_generic_to_shared(smem_dst);
    asm volatile("cp.async.cg.shared.global [%0], [%1], 16;\n"
                 :: "r"(s), "l"(gmem_src) : "memory");
}
__device__ __forceinline__ void cp_async_commit_wait_all() {
    asm volatile("cp.async.commit_group;\n");
    asm volatile("cp.async.wait_group 0;\n" ::: "memory");
}

__global__ __launch_bounds__(NTHREADS, 8)
void sgns_kernel(const int* __restrict__ walk,
                 const int* __restrict__ neg,
                 const float* __restrict__ embed,
                 float* __restrict__ out,
                 float inv_total) {
    __shared__ float4 srow[ROWS_PER][NVEC];   // 42 x 512B = 21.5 KB
    __shared__ int    swalk[ROWS_PER];
    __shared__ int    sneg[ANC_PER * NNEG];   // 152 ints
    __shared__ float  wsum[NWARPS];

    const int bid  = blockIdx.x;
    const int wb   = bid >> 1;                // walk index
    const int base = (bid & 1) * ANC_PER;     // first anchor of this half
    const int tid  = threadIdx.x;
    const int lane = tid & 31;
    const int wid  = tid >> 5;

    if (tid < ROWS_PER)
        swalk[tid] = walk[(size_t)wb * L_WALK + base + tid];
    if (tid < ANC_PER * NNEG)
        sneg[tid] = neg[((size_t)wb * A_ANC + base) * NNEG + tid];
    __syncthreads();

    // Stage the 42 walk-row embeddings via cp.async: no dest registers, no
    // LDG->STS dependency, so all ~5-6 copies per thread are in flight at
    // once (vs MLP=1 with the ld/st loop). Flat index over 1344 float4s.
    for (int f = tid; f < STAGE_V; f += NTHREADS) {
        const int r = f >> 5;          // row    (f / NVEC)
        const int v = f & (NVEC - 1);  // vector (f % NVEC)
        const float4* src = (const float4*)(embed + (size_t)swalk[r] * DIM) + v;
        cp_async16(&srow[r][v], src);
    }
    cp_async_commit_wait_all();
    __syncthreads();

    float acc = 0.0f;   // per-lane partial (8 softplus lanes contribute)

    // One warp per anchor; warps stride over the 38 anchors of this half.
    for (int a = wid; a < ANC_PER; a += NWARPS) {
        // Issue the 4 random gathers first so DRAM latency overlaps pos work.
        const int i0 = sneg[a * NNEG + 0];
        const int i1 = sneg[a * NNEG + 1];
        const int i2 = sneg[a * NNEG + 2];
        const int i3 = sneg[a * NNEG + 3];
        const float4 v0 = __ldg((const float4*)(embed + (size_t)i0 * DIM) + lane);
        const float4 v1 = __ldg((const float4*)(embed + (size_t)i1 * DIM) + lane);
        const float4 v2 = __ldg((const float4*)(embed + (size_t)i2 * DIM) + lane);
        const float4 v3 = __ldg((const float4*)(embed + (size_t)i3 * DIM) + lane);

        const float4 va = srow[a][lane];

        // Positive contexts (smem, reused 5x per row).
        const float p0 = dot4(va, srow[a + 1][lane]);
        const float p1 = dot4(va, srow[a + 2][lane]);
        const float p2 = dot4(va, srow[a + 3][lane]);
        const float p3 = dot4(va, srow[a + 4][lane]);

        // Negative dots (consume the in-flight gathers).
        const float p4 = dot4(va, v0);
        const float p5 = dot4(va, v1);
        const float p6 = dot4(va, v2);
        const float p7 = dot4(va, v3);

        // Multi-value warp reduction: 9 shfls reduce all 8 dots.
        //   bit16 -> pos vs neg, bits {8,4} -> which of the 4 within group.
        float r10 = cmb(p0, p4, 16, lane);
        float r11 = cmb(p1, p5, 16, lane);
        float r12 = cmb(p2, p6, 16, lane);
        float r13 = cmb(p3, p7, 16, lane);
        float q0  = cmb(r10, r11, 8, lane);
        float q1  = cmb(r12, r13, 8, lane);
        float r   = cmb(q0, q1, 4, lane);
        r += __shfl_xor_sync(0xffffffffu, r, 2);
        r += __shfl_xor_sync(0xffffffffu, r, 1);

        // Lanes 0,4,8,...,28 each hold one of the 8 full dot products.
        // bit16 set => negative-sample logit (softplus(+x)), else softplus(-x).
        if ((lane & 3) == 0) {
            const float x = (lane & 16) ? r : -r;
            acc += softplus_f(x);
        }
    }

    acc = warp_reduce_sum(acc);
    if (lane == 0) wsum[wid] = acc;
    __syncthreads();

    if (tid == 0) {
        float s = 0.0f;
        #pragma unroll
        for (int i = 0; i < NWARPS; i++) s += wsum[i];
        atomicAdd(out, s * inv_total);
    }
}

extern "C" void kernel_launch(void* const* d_in, const int* in_sizes, int n_in,
                              void* d_out, int out_size) {
    const int*   walk  = (const int*)d_in[0];
    const int*   neg   = (const int*)d_in[1];
    const float* embed = (const float*)d_in[2];
    float*       out   = (float*)d_out;

    const int B = in_sizes[0] / L_WALK;                 // 1024
    const float inv_total = 1.0f / ((float)B * A_ANC * (W_WIN - 1 + NNEG));

    zero_kernel<<<1, 32>>>(out);
    sgns_kernel<<<B * SPLIT, NTHREADS>>>(walk, neg, embed, out, inv_total);
}

// round 11
// speedup vs baseline: 1.1821x; 1.1821x over previous
#include <cuda_runtime.h>
#include <cuda_bf16.h>

// Problem constants (fixed by dataset):
//   walk:  int32 [B=1024, L=80]
//   neg:   int32 [B=1024, A=76, NEG=4]
//   embed: f32   [1000000, D=128]
//   out:   f32 scalar = (sum softplus(-pos) + sum softplus(neg)) / (B*A*8)
#define L_WALK   80
#define W_WIN    5
#define A_ANC    (L_WALK - W_WIN + 1)     // 76
#define NNEG     4
#define DIM      128
#define NVEC     (DIM / 4)                // 32 float4 per row
#define NTHREADS 256
#define NWARPS   (NTHREADS / 32)

#define SPLIT    2
#define ANC_PER  (A_ANC / SPLIT)          // 38 anchors per block
#define ROWS_PER (ANC_PER + W_WIN - 1)    // 42 walk rows staged per block
#define STAGE_V  (ROWS_PER * NVEC)        // 1344 float4 copies per block

static __global__ void zero_kernel(float* out) {
    if (threadIdx.x == 0) out[0] = 0.0f;
}

__device__ __forceinline__ float warp_reduce_sum(float v) {
    v += __shfl_xor_sync(0xffffffffu, v, 16);
    v += __shfl_xor_sync(0xffffffffu, v, 8);
    v += __shfl_xor_sync(0xffffffffu, v, 4);
    v += __shfl_xor_sync(0xffffffffu, v, 2);
    v += __shfl_xor_sync(0xffffffffu, v, 1);
    return v;
}

// Pairwise combining reduce: lanes with (lane & off)==0 end up holding the
// a-reduction, lanes with the bit set hold the b-reduction.
__device__ __forceinline__ float cmb(float a, float b, int off, int lane) {
    float send = (lane & off) ? a : b;
    float keep = (lane & off) ? b : a;
    return keep + __shfl_xor_sync(0xffffffffu, send, off);
}

// softplus(x) = max(x,0) + log(1 + exp(-|x|)); fast-math variants are
// accurate to ~1e-7 absolute here, far inside the 1e-3 rel-err budget.
__device__ __forceinline__ float softplus_f(float x) {
    return fmaxf(x, 0.0f) + __logf(1.0f + __expf(-fabsf(x)));
}

__device__ __forceinline__ float dot4(float4 a, float4 b) {
    return a.x * b.x + a.y * b.y + a.z * b.z + a.w * b.w;
}

__global__ __launch_bounds__(NTHREADS, 8)
void sgns_kernel(const int* __restrict__ walk,
                 const int* __restrict__ neg,
                 const float* __restrict__ embed,
                 float* __restrict__ out,
                 float inv_total) {
    __shared__ float4 srow[ROWS_PER][NVEC];   // 42 x 512B = 21.5 KB
    __shared__ int    swalk[ROWS_PER];
    __shared__ int    sneg[ANC_PER * NNEG];   // 152 ints
    __shared__ float  wsum[NWARPS];

    const int bid  = blockIdx.x;
    const int wb   = bid >> 1;                // walk index
    const int base = (bid & 1) * ANC_PER;     // first anchor of this half
    const int tid  = threadIdx.x;
    const int lane = tid & 31;
    const int wid  = tid >> 5;

    if (tid < ROWS_PER)
        swalk[tid] = walk[(size_t)wb * L_WALK + base + tid];
    if (tid < ANC_PER * NNEG)
        sneg[tid] = neg[((size_t)wb * A_ANC + base) * NNEG + tid];
    __syncthreads();

    // Stage the 42 walk-row embeddings (1344 float4s, flat-indexed) with
    // batched independent LDGs: load 3 into temporaries, then 3 STS, twice.
    // Staging MLP goes 1 -> 3 on the same LDG/L1 path as before, with only
    // 12 transient prologue registers (no pressure on the 32-reg main loop).
    {
        // Batch 1: f = tid, tid+256, tid+512 — always < 1344, no guards.
        const int f0 = tid, f1 = tid + NTHREADS, f2 = tid + 2 * NTHREADS;
        const float4 t0 = __ldg((const float4*)(embed + (size_t)swalk[f0 >> 5] * DIM) + (f0 & 31));
        const float4 t1 = __ldg((const float4*)(embed + (size_t)swalk[f1 >> 5] * DIM) + (f1 & 31));
        const float4 t2 = __ldg((const float4*)(embed + (size_t)swalk[f2 >> 5] * DIM) + (f2 & 31));
        srow[f0 >> 5][f0 & 31] = t0;
        srow[f1 >> 5][f1 & 31] = t1;
        srow[f2 >> 5][f2 & 31] = t2;
    }
    {
        // Batch 2: f = tid+768, tid+1024, tid+1280 — only the last can exceed 1343.
        const int f3 = tid + 3 * NTHREADS, f4 = tid + 4 * NTHREADS, f5 = tid + 5 * NTHREADS;
        const float4 t3 = __ldg((const float4*)(embed + (size_t)swalk[f3 >> 5] * DIM) + (f3 & 31));
        const float4 t4 = __ldg((const float4*)(embed + (size_t)swalk[f4 >> 5] * DIM) + (f4 & 31));
        float4 t5;
        const bool ok5 = (f5 < STAGE_V);
        if (ok5) t5 = __ldg((const float4*)(embed + (size_t)swalk[f5 >> 5] * DIM) + (f5 & 31));
        srow[f3 >> 5][f3 & 31] = t3;
        srow[f4 >> 5][f4 & 31] = t4;
        if (ok5) srow[f5 >> 5][f5 & 31] = t5;
    }
    __syncthreads();

    float acc = 0.0f;   // per-lane partial (8 softplus lanes contribute)

    // One warp per anchor; warps stride over the 38 anchors of this half.
    for (int a = wid; a < ANC_PER; a += NWARPS) {
        // Issue the 4 random gathers first so DRAM latency overlaps pos work.
        const int i0 = sneg[a * NNEG + 0];
        const int i1 = sneg[a * NNEG + 1];
        const int i2 = sneg[a * NNEG + 2];
        const int i3 = sneg[a * NNEG + 3];
        const float4 v0 = __ldg((const float4*)(embed + (size_t)i0 * DIM) + lane);
        const float4 v1 = __ldg((const float4*)(embed + (size_t)i1 * DIM) + lane);
        const float4 v2 = __ldg((const float4*)(embed + (size_t)i2 * DIM) + lane);
        const float4 v3 = __ldg((const float4*)(embed + (size_t)i3 * DIM) + lane);

        const float4 va = srow[a][lane];

        // Positive contexts (smem, reused 5x per row).
        const float p0 = dot4(va, srow[a + 1][lane]);
        const float p1 = dot4(va, srow[a + 2][lane]);
        const float p2 = dot4(va, srow[a + 3][lane]);
        const float p3 = dot4(va, srow[a + 4][lane]);

        // Negative dots (consume the in-flight gathers).
        const float p4 = dot4(va, v0);
        const float p5 = dot4(va, v1);
        const float p6 = dot4(va, v2);
        const float p7 = dot4(va, v3);

        // Multi-value warp reduction: 9 shfls reduce all 8 dots.
        //   bit16 -> pos vs neg, bits {8,4} -> which of the 4 within group.
        float r10 = cmb(p0, p4, 16, lane);
        float r11 = cmb(p1, p5, 16, lane);
        float r12 = cmb(p2, p6, 16, lane);
        float r13 = cmb(p3, p7, 16, lane);
        float q0  = cmb(r10, r11, 8, lane);
        float q1  = cmb(r12, r13, 8, lane);
        float r   = cmb(q0, q1, 4, lane);
        r += __shfl_xor_sync(0xffffffffu, r, 2);
        r += __shfl_xor_sync(0xffffffffu, r, 1);

        // Lanes 0,4,8,...,28 each hold one of the 8 full dot products.
        // bit16 set => negative-sample logit (softplus(+x)), else softplus(-x).
        if ((lane & 3) == 0) {
            const float x = (lane & 16) ? r : -r;
            acc += softplus_f(x);
        }
    }

    acc = warp_reduce_sum(acc);
    if (lane == 0) wsum[wid] = acc;
    __syncthreads();

    if (tid == 0) {
        float s = 0.0f;
        #pragma unroll
        for (int i = 0; i < NWARPS; i++) s += wsum[i];
        atomicAdd(out, s * inv_total);
    }
}

extern "C" void kernel_launch(void* const* d_in, const int* in_sizes, int n_in,
                              void* d_out, int out_size) {
    const int*   walk  = (const int*)d_in[0];
    const int*   neg   = (const int*)d_in[1];
    const float* embed = (const float*)d_in[2];
    float*       out   = (float*)d_out;

    const int B = in_sizes[0] / L_WALK;                 // 1024
    const float inv_total = 1.0f / ((float)B * A_ANC * (W_WIN - 1 + NNEG));

    zero_kernel<<<1, 32>>>(out);
    sgns_kernel<<<B * SPLIT, NTHREADS>>>(walk, neg, embed, out, inv_total);
}

// round 12
// speedup vs baseline: 1.1831x; 1.0009x over previous
#include <cuda_runtime.h>
#include <cuda_bf16.h>
#include <cstdint>

// Problem constants (fixed by dataset):
//   walk:  int32 [B=1024, L=80]
//   neg:   int32 [B=1024, A=76, NEG=4]
//   embed: f32   [1000000, D=128]
//   out:   f32 scalar = (sum softplus(-pos) + sum softplus(neg)) / (B*A*8)
#define L_WALK   80
#define W_WIN    5
#define A_ANC    (L_WALK - W_WIN + 1)     // 76
#define NNEG     4
#define DIM      128
#define NVEC     (DIM / 4)                // 32 float4 per row
#define NTHREADS 256
#define NWARPS   (NTHREADS / 32)

#define SPLIT    2
#define ANC_PER  (A_ANC / SPLIT)          // 38 anchors per block
#define ROWS_PER (ANC_PER + W_WIN - 1)    // 42 walk rows staged per block
#define STAGE_V  (ROWS_PER * NVEC)        // 1344 float4 copies per block
#define PREF     2                        // neg rows 2,3 prefetched via cp.async

static __global__ void zero_kernel(float* out) {
    if (threadIdx.x == 0) out[0] = 0.0f;
}

__device__ __forceinline__ float warp_reduce_sum(float v) {
    v += __shfl_xor_sync(0xffffffffu, v, 16);
    v += __shfl_xor_sync(0xffffffffu, v, 8);
    v += __shfl_xor_sync(0xffffffffu, v, 4);
    v += __shfl_xor_sync(0xffffffffu, v, 2);
    v += __shfl_xor_sync(0xffffffffu, v, 1);
    return v;
}

// Pairwise combining reduce: lanes with (lane & off)==0 end up holding the
// a-reduction, lanes with the bit set hold the b-reduction.
__device__ __forceinline__ float cmb(float a, float b, int off, int lane) {
    float send = (lane & off) ? a : b;
    float keep = (lane & off) ? b : a;
    return keep + __shfl_xor_sync(0xffffffffu, send, off);
}

// softplus(x) = max(x,0) + log(1 + exp(-|x|)); fast-math variants are
// accurate to ~1e-7 absolute here, far inside the 1e-3 rel-err budget.
__device__ __forceinline__ float softplus_f(float x) {
    return fmaxf(x, 0.0f) + __logf(1.0f + __expf(-fabsf(x)));
}

__device__ __forceinline__ float dot4(float4 a, float4 b) {
    return a.x * b.x + a.y * b.y + a.z * b.z + a.w * b.w;
}

// 16-byte global->shared async copy (LDGSTS): no destination register, so
// prefetching through it costs ZERO occupancy-relevant registers.
__device__ __forceinline__ void cp_async16(void* smem_dst, const void* gmem_src) {
    uint32_t s = (uint32_t)__cvta_generic_to_shared(smem_dst);
    asm volatile("cp.async.cg.shared.global [%0], [%1], 16;\n"
                 :: "r"(s), "l"(gmem_src) : "memory");
}
__device__ __forceinline__ void cp_async_commit() {
    asm volatile("cp.async.commit_group;\n" ::: "memory");
}
__device__ __forceinline__ void cp_async_wait_all() {
    asm volatile("cp.async.wait_group 0;\n" ::: "memory");
}

__global__ __launch_bounds__(NTHREADS, 7)
void sgns_kernel(const int* __restrict__ walk,
                 const int* __restrict__ neg,
                 const float* __restrict__ embed,
                 float* __restrict__ out,
                 float inv_total) {
    __shared__ float4 srow[ROWS_PER][NVEC];        // 42 x 512B = 21.5 KB
    __shared__ float4 nbuf[NWARPS][PREF][NVEC];    // per-warp prefetch, 8 KB
    __shared__ int    swalk[ROWS_PER];
    __shared__ int    sneg[ANC_PER * NNEG];        // 152 ints
    __shared__ float  wsum[NWARPS];

    const int bid  = blockIdx.x;
    const int wb   = bid >> 1;                // walk index
    const int base = (bid & 1) * ANC_PER;     // first anchor of this half
    const int tid  = threadIdx.x;
    const int lane = tid & 31;
    const int wid  = tid >> 5;

    if (tid < ROWS_PER)
        swalk[tid] = walk[(size_t)wb * L_WALK + base + tid];
    if (tid < ANC_PER * NNEG)
        sneg[tid] = neg[((size_t)wb * A_ANC + base) * NNEG + tid];
    __syncthreads();

    // Stage the 42 walk-row embeddings (1344 float4s, flat-indexed) with
    // batched independent LDGs (MLP=3 per batch) -- R9's proven prologue.
    {
        const int f0 = tid, f1 = tid + NTHREADS, f2 = tid + 2 * NTHREADS;
        const float4 t0 = __ldg((const float4*)(embed + (size_t)swalk[f0 >> 5] * DIM) + (f0 & 31));
        const float4 t1 = __ldg((const float4*)(embed + (size_t)swalk[f1 >> 5] * DIM) + (f1 & 31));
        const float4 t2 = __ldg((const float4*)(embed + (size_t)swalk[f2 >> 5] * DIM) + (f2 & 31));
        srow[f0 >> 5][f0 & 31] = t0;
        srow[f1 >> 5][f1 & 31] = t1;
        srow[f2 >> 5][f2 & 31] = t2;
    }
    {
        const int f3 = tid + 3 * NTHREADS, f4 = tid + 4 * NTHREADS, f5 = tid + 5 * NTHREADS;
        const float4 t3 = __ldg((const float4*)(embed + (size_t)swalk[f3 >> 5] * DIM) + (f3 & 31));
        const float4 t4 = __ldg((const float4*)(embed + (size_t)swalk[f4 >> 5] * DIM) + (f4 & 31));
        float4 t5;
        const bool ok5 = (f5 < STAGE_V);
        if (ok5) t5 = __ldg((const float4*)(embed + (size_t)swalk[f5 >> 5] * DIM) + (f5 & 31));
        srow[f3 >> 5][f3 & 31] = t3;
        srow[f4 >> 5][f4 & 31] = t4;
        if (ok5) srow[f5 >> 5][f5 & 31] = t5;
    }

    // Prologue prefetch: neg rows 2,3 of this warp's FIRST anchor go into the
    // per-warp smem buffer via cp.async (in flight while we finish staging).
    {
        const int a0 = wid;   // NWARPS(8) <= ANC_PER(38), always valid
        cp_async16(&nbuf[wid][0][lane],
                   (const float4*)(embed + (size_t)sneg[a0 * NNEG + 2] * DIM) + lane);
        cp_async16(&nbuf[wid][1][lane],
                   (const float4*)(embed + (size_t)sneg[a0 * NNEG + 3] * DIM) + lane);
        cp_async_commit();
    }
    __syncthreads();

    float acc = 0.0f;   // per-lane partial (8 softplus lanes contribute)

    // One warp per anchor. Per iteration: rows 0,1 gathered via LDG at the
    // top (~150cyc lead over their use); rows 2,3 were cp.async-prefetched a
    // FULL iteration ago (~450cyc lead) into this warp's private buffer.
    for (int a = wid; a < ANC_PER; a += NWARPS) {
        const int i0 = sneg[a * NNEG + 0];
        const int i1 = sneg[a * NNEG + 1];
        const float4 v0 = __ldg((const float4*)(embed + (size_t)i0 * DIM) + lane);
        const float4 v1 = __ldg((const float4*)(embed + (size_t)i1 * DIM) + lane);

        const float4 va = srow[a][lane];

        // Positive contexts (smem, reused 5x per row).
        const float p0 = dot4(va, srow[a + 1][lane]);
        const float p1 = dot4(va, srow[a + 2][lane]);
        const float p2 = dot4(va, srow[a + 3][lane]);
        const float p3 = dot4(va, srow[a + 4][lane]);

        // Consume prefetched rows 2,3 (issued last iteration; long complete).
        cp_async_wait_all();
        const float4 v2 = nbuf[wid][0][lane];
        const float4 v3 = nbuf[wid][1][lane];

        const float p4 = dot4(va, v0);
        const float p5 = dot4(va, v1);
        const float p6 = dot4(va, v2);
        const float p7 = dot4(va, v3);

        // Refill the buffer with the NEXT anchor's rows 2,3. The LDS reads of
        // nbuf above complete in ~29cyc; the earliest these copies can write
        // smem is one L2/DRAM latency (>=250cyc) after issue — no overlap.
        const int  an = a + NWARPS;
        if (an < ANC_PER) {   // warp-uniform
            cp_async16(&nbuf[wid][0][lane],
                       (const float4*)(embed + (size_t)sneg[an * NNEG + 2] * DIM) + lane);
            cp_async16(&nbuf[wid][1][lane],
                       (const float4*)(embed + (size_t)sneg[an * NNEG + 3] * DIM) + lane);
            cp_async_commit();
        }

        // Multi-value warp reduction: 9 shfls reduce all 8 dots.
        //   bit16 -> pos vs neg, bits {8,4} -> which of the 4 within group.
        // The 2 LDGSTS above stay in flight through this whole tail.
        float r10 = cmb(p0, p4, 16, lane);
        float r11 = cmb(p1, p5, 16, lane);
        float r12 = cmb(p2, p6, 16, lane);
        float r13 = cmb(p3, p7, 16, lane);
        float q0  = cmb(r10, r11, 8, lane);
        float q1  = cmb(r12, r13, 8, lane);
        float r   = cmb(q0, q1, 4, lane);
        r += __shfl_xor_sync(0xffffffffu, r, 2);
        r += __shfl_xor_sync(0xffffffffu, r, 1);

        // Lanes 0,4,8,...,28 each hold one of the 8 full dot products.
        // bit16 set => negative-sample logit (softplus(+x)), else softplus(-x).
        if ((lane & 3) == 0) {
            const float x = (lane & 16) ? r : -r;
            acc += softplus_f(x);
        }
    }

    acc = warp_reduce_sum(acc);
    if (lane == 0) wsum[wid] = acc;
    __syncthreads();

    if (tid == 0) {
        float s = 0.0f;
        #pragma unroll
        for (int i = 0; i < NWARPS; i++) s += wsum[i];
        atomicAdd(out, s * inv_total);
    }
}

extern "C" void kernel_launch(void* const* d_in, const int* in_sizes, int n_in,
                              void* d_out, int out_size) {
    const int*   walk  = (const int*)d_in[0];
    const int*   neg   = (const int*)d_in[1];
    const float* embed = (const float*)d_in[2];
    float*       out   = (float*)d_out;

    const int B = in_sizes[0] / L_WALK;                 // 1024
    const float inv_total = 1.0f / ((float)B * A_ANC * (W_WIN - 1 + NNEG));

    zero_kernel<<<1, 32>>>(out);
    sgns_kernel<<<B * SPLIT, NTHREADS>>>(walk, neg, embed, out, inv_total);
}